// round 15
// baseline (speedup 1.0000x reference)
#include <cuda_runtime.h>
#include <cstdint>

// ============================================================================
// SDPA_31671088841439 — GB300 baseline
//   h = x@W_in^T + b; q/k/v = h@W^T; S = 0.25*q@k^T;
//   P = softmax(S, axis=0); out = P@v; result = sum(logcosh(out), -1)
// Strategy: staged fp32 GEMMs using packed fma.rn.f32x2 (2x FFMA throughput
// on sm_103a), column softmax with FMA-pipe polynomial exp (MUFU avoided),
// 1/Z folded into v rows so the second big GEMM stays pure.
// ============================================================================

#define NROW  8192
#define NSPIN 1024
#define NHID  1024
#define CH    16            // row chunks for column reductions
#define RPC   (NROW / CH)   // 512 rows per chunk

// ---------------- scratch (single __device__ global; no allocations) --------
constexpr size_t SZ_S  = (size_t)NROW * NROW;       // 67,108,864
constexpr size_t SZ_NH = (size_t)NROW * NHID;       //  8,388,608
constexpr size_t OFF_S  = 0;
constexpr size_t OFF_H  = OFF_S + SZ_S;
constexpr size_t OFF_Q  = OFF_H + SZ_NH;
constexpr size_t OFF_K  = OFF_Q + SZ_NH;
constexpr size_t OFF_V  = OFF_K + SZ_NH;
constexpr size_t OFF_O  = OFF_V + SZ_NH;
constexpr size_t OFF_PM = OFF_O + SZ_NH;
constexpr size_t OFF_PZ = OFF_PM + (size_t)CH * NROW;
constexpr size_t OFF_M  = OFF_PZ + (size_t)CH * NROW;
constexpr size_t OFF_RZ = OFF_M + NROW;
constexpr size_t SCRATCH_TOTAL = OFF_RZ + NROW;

__device__ float g_scratch[SCRATCH_TOTAL];

// ---------------- packed fp32x2 helpers -------------------------------------
__device__ __forceinline__ unsigned long long pack_dup(float x) {
    unsigned long long r;
    asm("mov.b64 %0, {%1, %1};" : "=l"(r) : "f"(x));
    return r;
}
__device__ __forceinline__ unsigned long long pack2(float x, float y) {
    unsigned long long r;
    asm("mov.b64 %0, {%1, %2};" : "=l"(r) : "f"(x), "f"(y));
    return r;
}
__device__ __forceinline__ void ffma2(unsigned long long& d,
                                      unsigned long long a,
                                      unsigned long long b) {
    asm("fma.rn.f32x2 %0, %1, %2, %0;" : "+l"(d) : "l"(a), "l"(b));
}
__device__ __forceinline__ void unpack2(unsigned long long v, float& lo, float& hi) {
    asm("mov.b64 {%0, %1}, %2;" : "=f"(lo), "=f"(hi) : "l"(v));
}

// ---------------- fast exp on the FMA pipe (args <= 0 in all uses) ----------
// exp(x) = 2^(x*log2e); n = rint(t), r = t-n in [-0.5,0.5]; degree-5 poly for
// 2^r (rel err ~2.4e-6); scale via exponent-bit construction. Clamp t >= -126
// so (n+127) stays a valid normal exponent (underflow -> ~1e-38 ~ 0).
__device__ __forceinline__ float fast_exp(float x) {
    float t = x * 1.4426950408889634f;
    t = fmaxf(t, -126.0f);
    float n = rintf(t);
    float r = t - n;
    float p = 1.3333558e-3f;
    p = fmaf(p, r, 9.6181291e-3f);
    p = fmaf(p, r, 5.5504109e-2f);
    p = fmaf(p, r, 2.4022651e-1f);
    p = fmaf(p, r, 6.9314718e-1f);
    p = fmaf(p, r, 1.0f);
    float s = __int_as_float(((int)n + 127) << 23);
    return p * s;
}

// ============================================================================
// GEMM: C[M,Nn] = alpha * A[M,K] @ op(B) (+ bias[Nn])
//   BT=true : B is [Nn,K] row-major (A@B^T, both K-contiguous)
//   BT=false: B is [K,Nn] row-major (A@B)
// 128x128x8 block tile, 256 threads, 8x8 per thread via fma.rn.f32x2,
// double-buffered smem. All dims are multiples of the tile (8192/1024).
// ============================================================================
template<bool BT>
__global__ __launch_bounds__(256)
void gemm_kernel(const float* __restrict__ A, const float* __restrict__ B,
                 float* __restrict__ C, const float* __restrict__ bias,
                 float alpha, int M, int Nn, int K)
{
    constexpr int BM = 128, BN = 128, BK = 8, PAD = 8;
    __shared__ float As[2][BK][BM + PAD];
    __shared__ float Bs[2][BK][BN + PAD];

    const int tid = threadIdx.x;
    const size_t bm = (size_t)blockIdx.y * BM;
    const size_t bn = (size_t)blockIdx.x * BN;

    // loaders: K-major operands (A always; B when BT): 128 rows x 2 quads
    const int lr = tid >> 1;          // 0..127
    const int lc = (tid & 1) << 2;    // 0 or 4
    // N-major B (NN): 8 rows x 32 quads
    const int nr = tid >> 5;          // 0..7
    const int nc = (tid & 31) << 2;   // 0..124

    // compute mapping: rows ty*8+[0,8), cols {tx*4+[0,4), 64+tx*4+[0,4)}
    const int tx = tid & 15;
    const int ty = tid >> 4;

    const float* Aptr = A + (bm + (size_t)lr) * (size_t)K + lc;
    const float* Bptr = BT ? (B + (bn + (size_t)lr) * (size_t)K + lc)
                           : (B + (size_t)nr * (size_t)Nn + bn + nc);

    unsigned long long acc[8][4];
    #pragma unroll
    for (int i = 0; i < 8; i++)
        #pragma unroll
        for (int j = 0; j < 4; j++) acc[i][j] = 0ULL;

    const int ktiles = K / BK;

    // prologue: tile 0
    float4 aV = *(const float4*)Aptr;
    float4 bV = *(const float4*)Bptr;
    As[0][lc + 0][lr] = aV.x; As[0][lc + 1][lr] = aV.y;
    As[0][lc + 2][lr] = aV.z; As[0][lc + 3][lr] = aV.w;
    if (BT) {
        Bs[0][lc + 0][lr] = bV.x; Bs[0][lc + 1][lr] = bV.y;
        Bs[0][lc + 2][lr] = bV.z; Bs[0][lc + 3][lr] = bV.w;
    } else {
        *(float4*)&Bs[0][nr][nc] = bV;
    }
    __syncthreads();

    int buf = 0;
    for (int kt = 0; kt < ktiles; kt++) {
        if (kt + 1 < ktiles) {
            aV = *(const float4*)(Aptr + (size_t)(kt + 1) * BK);
            if (BT) bV = *(const float4*)(Bptr + (size_t)(kt + 1) * BK);
            else    bV = *(const float4*)(Bptr + (size_t)(kt + 1) * BK * (size_t)Nn);
        }
        #pragma unroll
        for (int k = 0; k < BK; k++) {
            const float4 af0 = *(const float4*)&As[buf][k][ty * 8];
            const float4 af1 = *(const float4*)&As[buf][k][ty * 8 + 4];
            unsigned long long av[8];
            av[0] = pack_dup(af0.x); av[1] = pack_dup(af0.y);
            av[2] = pack_dup(af0.z); av[3] = pack_dup(af0.w);
            av[4] = pack_dup(af1.x); av[5] = pack_dup(af1.y);
            av[6] = pack_dup(af1.z); av[7] = pack_dup(af1.w);
            const float4 bf0 = *(const float4*)&Bs[buf][k][tx * 4];
            const float4 bf1 = *(const float4*)&Bs[buf][k][64 + tx * 4];
            unsigned long long bv[4];
            bv[0] = pack2(bf0.x, bf0.y); bv[1] = pack2(bf0.z, bf0.w);
            bv[2] = pack2(bf1.x, bf1.y); bv[3] = pack2(bf1.z, bf1.w);
            #pragma unroll
            for (int i = 0; i < 8; i++) {
                ffma2(acc[i][0], av[i], bv[0]);
                ffma2(acc[i][1], av[i], bv[1]);
                ffma2(acc[i][2], av[i], bv[2]);
                ffma2(acc[i][3], av[i], bv[3]);
            }
        }
        if (kt + 1 < ktiles) {
            const int nb = buf ^ 1;
            As[nb][lc + 0][lr] = aV.x; As[nb][lc + 1][lr] = aV.y;
            As[nb][lc + 2][lr] = aV.z; As[nb][lc + 3][lr] = aV.w;
            if (BT) {
                Bs[nb][lc + 0][lr] = bV.x; Bs[nb][lc + 1][lr] = bV.y;
                Bs[nb][lc + 2][lr] = bV.z; Bs[nb][lc + 3][lr] = bV.w;
            } else {
                *(float4*)&Bs[nb][nr][nc] = bV;
            }
        }
        __syncthreads();
        buf ^= 1;
    }

    // epilogue
    #pragma unroll
    for (int i = 0; i < 8; i++) {
        float* crow = C + (bm + (size_t)(ty * 8 + i)) * (size_t)Nn + bn;
        #pragma unroll
        for (int h = 0; h < 2; h++) {
            const int col = h * 64 + tx * 4;
            float x0, x1, x2, x3;
            unpack2(acc[i][h * 2 + 0], x0, x1);
            unpack2(acc[i][h * 2 + 1], x2, x3);
            float4 o;
            o.x = alpha * x0; o.y = alpha * x1;
            o.z = alpha * x2; o.w = alpha * x3;
            if (bias != nullptr) {
                const float4 bb = *(const float4*)&bias[bn + col];
                o.x += bb.x; o.y += bb.y; o.z += bb.z; o.w += bb.w;
            }
            *(float4*)&crow[col] = o;
        }
    }
}

// ============================================================================
// Column softmax (axis=0): per column j over rows i of S[8192,8192]
// ============================================================================
__global__ void colmax_part(const float* __restrict__ S, float* __restrict__ pm) {
    const int j = blockIdx.x * blockDim.x + threadIdx.x;
    const int c = blockIdx.y;
    const float* p = S + (size_t)c * RPC * NROW + j;
    float m0 = -3.4e38f, m1 = m0, m2 = m0, m3 = m0;
    float m4 = m0, m5 = m0, m6 = m0, m7 = m0;
    for (int i = 0; i < RPC; i += 8) {
        m0 = fmaxf(m0, p[(size_t)(i + 0) * NROW]);
        m1 = fmaxf(m1, p[(size_t)(i + 1) * NROW]);
        m2 = fmaxf(m2, p[(size_t)(i + 2) * NROW]);
        m3 = fmaxf(m3, p[(size_t)(i + 3) * NROW]);
        m4 = fmaxf(m4, p[(size_t)(i + 4) * NROW]);
        m5 = fmaxf(m5, p[(size_t)(i + 5) * NROW]);
        m6 = fmaxf(m6, p[(size_t)(i + 6) * NROW]);
        m7 = fmaxf(m7, p[(size_t)(i + 7) * NROW]);
    }
    pm[(size_t)c * NROW + j] =
        fmaxf(fmaxf(fmaxf(m0, m1), fmaxf(m2, m3)),
              fmaxf(fmaxf(m4, m5), fmaxf(m6, m7)));
}

__global__ void colmax_reduce(const float* __restrict__ pm, float* __restrict__ m) {
    const int j = blockIdx.x * blockDim.x + threadIdx.x;
    float mx = pm[j];
    #pragma unroll
    for (int c = 1; c < CH; c++) mx = fmaxf(mx, pm[(size_t)c * NROW + j]);
    m[j] = mx;
}

// P = exp(S - m[j]) written in place; per-chunk partial column sums
__global__ void expsum_part(float* __restrict__ S, const float* __restrict__ m,
                            float* __restrict__ pz) {
    const int j = blockIdx.x * blockDim.x + threadIdx.x;
    const int c = blockIdx.y;
    const float mj = m[j];
    float* p = S + (size_t)c * RPC * NROW + j;
    float z0 = 0.f, z1 = 0.f, z2 = 0.f, z3 = 0.f;
    for (int i = 0; i < RPC; i += 4) {
        float e0 = fast_exp(p[(size_t)(i + 0) * NROW] - mj);
        float e1 = fast_exp(p[(size_t)(i + 1) * NROW] - mj);
        float e2 = fast_exp(p[(size_t)(i + 2) * NROW] - mj);
        float e3 = fast_exp(p[(size_t)(i + 3) * NROW] - mj);
        p[(size_t)(i + 0) * NROW] = e0;
        p[(size_t)(i + 1) * NROW] = e1;
        p[(size_t)(i + 2) * NROW] = e2;
        p[(size_t)(i + 3) * NROW] = e3;
        z0 += e0; z1 += e1; z2 += e2; z3 += e3;
    }
    pz[(size_t)c * NROW + j] = (z0 + z1) + (z2 + z3);
}

__global__ void zreduce(const float* __restrict__ pz, float* __restrict__ rz) {
    const int j = blockIdx.x * blockDim.x + threadIdx.x;
    float z = 0.f;
    #pragma unroll
    for (int c = 0; c < CH; c++) z += pz[(size_t)c * NROW + j];
    rz[j] = 1.0f / z;
}

// v'[j,h] = v[j,h] / Z[j]  (fold softmax denominator into v rows)
__global__ void scale_v(float* __restrict__ v, const float* __restrict__ rz) {
    const size_t idx = (size_t)blockIdx.x * blockDim.x + threadIdx.x;
    v[idx] *= rz[idx >> 10];  // NHID = 1024
}

// ============================================================================
// result[i] = sum_h logcosh(o[i,h]) ; logcosh(z)=|z|+log1p(exp(-2|z|))-ln2
// ============================================================================
__global__ void logcosh_rows(const float* __restrict__ o, float* __restrict__ out) {
    const int i = blockIdx.x;
    const float* r = o + (size_t)i * NHID;
    float s = 0.f;
    for (int h = threadIdx.x; h < NHID; h += 256) {
        const float a = fabsf(r[h]);
        s += a + log1pf(fast_exp(-2.0f * a));
    }
    #pragma unroll
    for (int off = 16; off > 0; off >>= 1)
        s += __shfl_xor_sync(0xffffffffu, s, off);
    __shared__ float red[8];
    if ((threadIdx.x & 31) == 0) red[threadIdx.x >> 5] = s;
    __syncthreads();
    if (threadIdx.x == 0) {
        float t = 0.f;
        #pragma unroll
        for (int w = 0; w < 8; w++) t += red[w];
        out[i] = t - (float)NHID * 0.6931471805599453f;
    }
}

// ============================================================================
// launch
// ============================================================================
extern "C" void kernel_launch(void* const* d_in, const int* in_sizes, int n_in,
                              void* d_out, int out_size) {
    (void)in_sizes; (void)n_in; (void)out_size;
    const float* x   = (const float*)d_in[0];
    const float* Win = (const float*)d_in[1];
    const float* bin = (const float*)d_in[2];
    const float* Wq  = (const float*)d_in[3];
    const float* Wk  = (const float*)d_in[4];
    const float* Wv  = (const float*)d_in[5];
    float* out = (float*)d_out;

    float* base = nullptr;
    cudaGetSymbolAddress((void**)&base, g_scratch);
    float* S  = base + OFF_S;
    float* h  = base + OFF_H;
    float* q  = base + OFF_Q;
    float* k  = base + OFF_K;
    float* v  = base + OFF_V;
    float* o  = base + OFF_O;
    float* pm = base + OFF_PM;
    float* pz = base + OFF_PZ;
    float* m  = base + OFF_M;
    float* rz = base + OFF_RZ;

    // embedding + q/k/v projections (NT GEMMs, K=1024)
    gemm_kernel<true><<<dim3(NHID / 128, NROW / 128), 256>>>(
        x, Win, h, bin, 1.0f, NROW, NHID, NSPIN);
    gemm_kernel<true><<<dim3(NHID / 128, NROW / 128), 256>>>(
        h, Wq, q, nullptr, 1.0f, NROW, NHID, NHID);
    gemm_kernel<true><<<dim3(NHID / 128, NROW / 128), 256>>>(
        h, Wk, k, nullptr, 1.0f, NROW, NHID, NHID);
    gemm_kernel<true><<<dim3(NHID / 128, NROW / 128), 256>>>(
        h, Wv, v, nullptr, 1.0f, NROW, NHID, NHID);

    // scores S = 0.25 * q @ k^T   [8192, 8192]
    gemm_kernel<true><<<dim3(NROW / 128, NROW / 128), 256>>>(
        q, k, S, nullptr, 0.25f, NROW, NROW, NHID);

    // column softmax stats + in-place P = exp(S - m[j]); fold 1/Z into v
    colmax_part<<<dim3(NROW / 256, CH), 256>>>(S, pm);
    colmax_reduce<<<NROW / 256, 256>>>(pm, m);
    expsum_part<<<dim3(NROW / 256, CH), 256>>>(S, m, pz);
    zreduce<<<NROW / 256, 256>>>(pz, rz);
    scale_v<<<(NROW * NHID) / 256, 256>>>(v, rz);

    // out = P @ v'   (NN GEMM, K=8192)
    gemm_kernel<false><<<dim3(NHID / 128, NROW / 128), 256>>>(
        S, v, o, nullptr, 1.0f, NROW, NHID, NROW);

    // row-wise sum of logcosh
    logcosh_rows<<<NROW, 256>>>(o, out);
}

// round 16
// speedup vs baseline: 1.0002x; 1.0002x over previous
#include <cuda_runtime.h>
#include <cstdint>

// ============================================================================
// SDPA_31671088841439 — GB300 baseline
//   h = x@W_in^T + b; q/k/v = h@W^T; S = 0.25*q@k^T;
//   P = softmax(S, axis=0); out = P@v; result = sum(logcosh(out), -1)
// Strategy: staged fp32 GEMMs using packed fma.rn.f32x2 (2x FFMA throughput
// on sm_103a), column softmax with FMA-pipe polynomial exp (MUFU avoided),
// 1/Z folded into v rows so the second big GEMM stays pure.
// ============================================================================

#define NROW  8192
#define NSPIN 1024
#define NHID  1024
#define CH    16            // row chunks for column reductions
#define RPC   (NROW / CH)   // 512 rows per chunk

// ---------------- scratch (single __device__ global; no allocations) --------
constexpr size_t SZ_S  = (size_t)NROW * NROW;       // 67,108,864
constexpr size_t SZ_NH = (size_t)NROW * NHID;       //  8,388,608
constexpr size_t OFF_S  = 0;
constexpr size_t OFF_H  = OFF_S + SZ_S;
constexpr size_t OFF_Q  = OFF_H + SZ_NH;
constexpr size_t OFF_K  = OFF_Q + SZ_NH;
constexpr size_t OFF_V  = OFF_K + SZ_NH;
constexpr size_t OFF_O  = OFF_V + SZ_NH;
constexpr size_t OFF_PM = OFF_O + SZ_NH;
constexpr size_t OFF_PZ = OFF_PM + (size_t)CH * NROW;
constexpr size_t OFF_M  = OFF_PZ + (size_t)CH * NROW;
constexpr size_t OFF_RZ = OFF_M + NROW;
constexpr size_t SCRATCH_TOTAL = OFF_RZ + NROW;

__device__ float g_scratch[SCRATCH_TOTAL];

// ---------------- packed fp32x2 helpers -------------------------------------
__device__ __forceinline__ unsigned long long pack_dup(float x) {
    unsigned long long r;
    asm("mov.b64 %0, {%1, %1};" : "=l"(r) : "f"(x));
    return r;
}
__device__ __forceinline__ unsigned long long pack2(float x, float y) {
    unsigned long long r;
    asm("mov.b64 %0, {%1, %2};" : "=l"(r) : "f"(x), "f"(y));
    return r;
}
__device__ __forceinline__ void ffma2(unsigned long long& d,
                                      unsigned long long a,
                                      unsigned long long b) {
    asm("fma.rn.f32x2 %0, %1, %2, %0;" : "+l"(d) : "l"(a), "l"(b));
}
__device__ __forceinline__ void unpack2(unsigned long long v, float& lo, float& hi) {
    asm("mov.b64 {%0, %1}, %2;" : "=f"(lo), "=f"(hi) : "l"(v));
}

// ---------------- fast exp on the FMA pipe (args <= 0 in all uses) ----------
// exp(x) = 2^(x*log2e); n = rint(t), r = t-n in [-0.5,0.5]; degree-5 poly for
// 2^r (rel err ~2.4e-6); scale via exponent-bit construction. Clamp t >= -126
// so (n+127) stays a valid normal exponent (underflow -> ~1e-38 ~ 0).
__device__ __forceinline__ float fast_exp(float x) {
    float t = x * 1.4426950408889634f;
    t = fmaxf(t, -126.0f);
    float n = rintf(t);
    float r = t - n;
    float p = 1.3333558e-3f;
    p = fmaf(p, r, 9.6181291e-3f);
    p = fmaf(p, r, 5.5504109e-2f);
    p = fmaf(p, r, 2.4022651e-1f);
    p = fmaf(p, r, 6.9314718e-1f);
    p = fmaf(p, r, 1.0f);
    float s = __int_as_float(((int)n + 127) << 23);
    return p * s;
}

// ============================================================================
// GEMM: C[M,Nn] = alpha * A[M,K] @ op(B) (+ bias[Nn])
//   BT=true : B is [Nn,K] row-major (A@B^T, both K-contiguous)
//   BT=false: B is [K,Nn] row-major (A@B)
// 128x128x8 block tile, 256 threads, 8x8 per thread via fma.rn.f32x2,
// double-buffered smem. All dims are multiples of the tile (8192/1024).
// ============================================================================
template<bool BT>
__global__ __launch_bounds__(256)
void gemm_kernel(const float* __restrict__ A, const float* __restrict__ B,
                 float* __restrict__ C, const float* __restrict__ bias,
                 float alpha, int M, int Nn, int K)
{
    constexpr int BM = 128, BN = 128, BK = 8, PAD = 8;
    __shared__ float As[2][BK][BM + PAD];
    __shared__ float Bs[2][BK][BN + PAD];

    const int tid = threadIdx.x;
    const size_t bm = (size_t)blockIdx.y * BM;
    const size_t bn = (size_t)blockIdx.x * BN;

    // loaders: K-major operands (A always; B when BT): 128 rows x 2 quads
    const int lr = tid >> 1;          // 0..127
    const int lc = (tid & 1) << 2;    // 0 or 4
    // N-major B (NN): 8 rows x 32 quads
    const int nr = tid >> 5;          // 0..7
    const int nc = (tid & 31) << 2;   // 0..124

    // compute mapping: rows ty*8+[0,8), cols {tx*4+[0,4), 64+tx*4+[0,4)}
    const int tx = tid & 15;
    const int ty = tid >> 4;

    const float* Aptr = A + (bm + (size_t)lr) * (size_t)K + lc;
    const float* Bptr = BT ? (B + (bn + (size_t)lr) * (size_t)K + lc)
                           : (B + (size_t)nr * (size_t)Nn + bn + nc);

    unsigned long long acc[8][4];
    #pragma unroll
    for (int i = 0; i < 8; i++)
        #pragma unroll
        for (int j = 0; j < 4; j++) acc[i][j] = 0ULL;

    const int ktiles = K / BK;

    // prologue: tile 0
    float4 aV = *(const float4*)Aptr;
    float4 bV = *(const float4*)Bptr;
    As[0][lc + 0][lr] = aV.x; As[0][lc + 1][lr] = aV.y;
    As[0][lc + 2][lr] = aV.z; As[0][lc + 3][lr] = aV.w;
    if (BT) {
        Bs[0][lc + 0][lr] = bV.x; Bs[0][lc + 1][lr] = bV.y;
        Bs[0][lc + 2][lr] = bV.z; Bs[0][lc + 3][lr] = bV.w;
    } else {
        *(float4*)&Bs[0][nr][nc] = bV;
    }
    __syncthreads();

    int buf = 0;
    for (int kt = 0; kt < ktiles; kt++) {
        if (kt + 1 < ktiles) {
            aV = *(const float4*)(Aptr + (size_t)(kt + 1) * BK);
            if (BT) bV = *(const float4*)(Bptr + (size_t)(kt + 1) * BK);
            else    bV = *(const float4*)(Bptr + (size_t)(kt + 1) * BK * (size_t)Nn);
        }
        #pragma unroll
        for (int k = 0; k < BK; k++) {
            const float4 af0 = *(const float4*)&As[buf][k][ty * 8];
            const float4 af1 = *(const float4*)&As[buf][k][ty * 8 + 4];
            unsigned long long av[8];
            av[0] = pack_dup(af0.x); av[1] = pack_dup(af0.y);
            av[2] = pack_dup(af0.z); av[3] = pack_dup(af0.w);
            av[4] = pack_dup(af1.x); av[5] = pack_dup(af1.y);
            av[6] = pack_dup(af1.z); av[7] = pack_dup(af1.w);
            const float4 bf0 = *(const float4*)&Bs[buf][k][tx * 4];
            const float4 bf1 = *(const float4*)&Bs[buf][k][64 + tx * 4];
            unsigned long long bv[4];
            bv[0] = pack2(bf0.x, bf0.y); bv[1] = pack2(bf0.z, bf0.w);
            bv[2] = pack2(bf1.x, bf1.y); bv[3] = pack2(bf1.z, bf1.w);
            #pragma unroll
            for (int i = 0; i < 8; i++) {
                ffma2(acc[i][0], av[i], bv[0]);
                ffma2(acc[i][1], av[i], bv[1]);
                ffma2(acc[i][2], av[i], bv[2]);
                ffma2(acc[i][3], av[i], bv[3]);
            }
        }
        if (kt + 1 < ktiles) {
            const int nb = buf ^ 1;
            As[nb][lc + 0][lr] = aV.x; As[nb][lc + 1][lr] = aV.y;
            As[nb][lc + 2][lr] = aV.z; As[nb][lc + 3][lr] = aV.w;
            if (BT) {
                Bs[nb][lc + 0][lr] = bV.x; Bs[nb][lc + 1][lr] = bV.y;
                Bs[nb][lc + 2][lr] = bV.z; Bs[nb][lc + 3][lr] = bV.w;
            } else {
                *(float4*)&Bs[nb][nr][nc] = bV;
            }
        }
        __syncthreads();
        buf ^= 1;
    }

    // epilogue
    #pragma unroll
    for (int i = 0; i < 8; i++) {
        float* crow = C + (bm + (size_t)(ty * 8 + i)) * (size_t)Nn + bn;
        #pragma unroll
        for (int h = 0; h < 2; h++) {
            const int col = h * 64 + tx * 4;
            float x0, x1, x2, x3;
            unpack2(acc[i][h * 2 + 0], x0, x1);
            unpack2(acc[i][h * 2 + 1], x2, x3);
            float4 o;
            o.x = alpha * x0; o.y = alpha * x1;
            o.z = alpha * x2; o.w = alpha * x3;
            if (bias != nullptr) {
                const float4 bb = *(const float4*)&bias[bn + col];
                o.x += bb.x; o.y += bb.y; o.z += bb.z; o.w += bb.w;
            }
            *(float4*)&crow[col] = o;
        }
    }
}

// ============================================================================
// Column softmax (axis=0): per column j over rows i of S[8192,8192]
// ============================================================================
__global__ void colmax_part(const float* __restrict__ S, float* __restrict__ pm) {
    const int j = blockIdx.x * blockDim.x + threadIdx.x;
    const int c = blockIdx.y;
    const float* p = S + (size_t)c * RPC * NROW + j;
    float m0 = -3.4e38f, m1 = m0, m2 = m0, m3 = m0;
    float m4 = m0, m5 = m0, m6 = m0, m7 = m0;
    for (int i = 0; i < RPC; i += 8) {
        m0 = fmaxf(m0, p[(size_t)(i + 0) * NROW]);
        m1 = fmaxf(m1, p[(size_t)(i + 1) * NROW]);
        m2 = fmaxf(m2, p[(size_t)(i + 2) * NROW]);
        m3 = fmaxf(m3, p[(size_t)(i + 3) * NROW]);
        m4 = fmaxf(m4, p[(size_t)(i + 4) * NROW]);
        m5 = fmaxf(m5, p[(size_t)(i + 5) * NROW]);
        m6 = fmaxf(m6, p[(size_t)(i + 6) * NROW]);
        m7 = fmaxf(m7, p[(size_t)(i + 7) * NROW]);
    }
    pm[(size_t)c * NROW + j] =
        fmaxf(fmaxf(fmaxf(m0, m1), fmaxf(m2, m3)),
              fmaxf(fmaxf(m4, m5), fmaxf(m6, m7)));
}

__global__ void colmax_reduce(const float* __restrict__ pm, float* __restrict__ m) {
    const int j = blockIdx.x * blockDim.x + threadIdx.x;
    float mx = pm[j];
    #pragma unroll
    for (int c = 1; c < CH; c++) mx = fmaxf(mx, pm[(size_t)c * NROW + j]);
    m[j] = mx;
}

// P = exp(S - m[j]) written in place; per-chunk partial column sums
__global__ void expsum_part(float* __restrict__ S, const float* __restrict__ m,
                            float* __restrict__ pz) {
    const int j = blockIdx.x * blockDim.x + threadIdx.x;
    const int c = blockIdx.y;
    const float mj = m[j];
    float* p = S + (size_t)c * RPC * NROW + j;
    float z0 = 0.f, z1 = 0.f, z2 = 0.f, z3 = 0.f;
    for (int i = 0; i < RPC; i += 4) {
        float e0 = fast_exp(p[(size_t)(i + 0) * NROW] - mj);
        float e1 = fast_exp(p[(size_t)(i + 1) * NROW] - mj);
        float e2 = fast_exp(p[(size_t)(i + 2) * NROW] - mj);
        float e3 = fast_exp(p[(size_t)(i + 3) * NROW] - mj);
        p[(size_t)(i + 0) * NROW] = e0;
        p[(size_t)(i + 1) * NROW] = e1;
        p[(size_t)(i + 2) * NROW] = e2;
        p[(size_t)(i + 3) * NROW] = e3;
        z0 += e0; z1 += e1; z2 += e2; z3 += e3;
    }
    pz[(size_t)c * NROW + j] = (z0 + z1) + (z2 + z3);
}

__global__ void zreduce(const float* __restrict__ pz, float* __restrict__ rz) {
    const int j = blockIdx.x * blockDim.x + threadIdx.x;
    float z = 0.f;
    #pragma unroll
    for (int c = 0; c < CH; c++) z += pz[(size_t)c * NROW + j];
    rz[j] = 1.0f / z;
}

// v'[j,h] = v[j,h] / Z[j]  (fold softmax denominator into v rows)
__global__ void scale_v(float* __restrict__ v, const float* __restrict__ rz) {
    const size_t idx = (size_t)blockIdx.x * blockDim.x + threadIdx.x;
    v[idx] *= rz[idx >> 10];  // NHID = 1024
}

// ============================================================================
// result[i] = sum_h logcosh(o[i,h]) ; logcosh(z)=|z|+log1p(exp(-2|z|))-ln2
// ============================================================================
__global__ void logcosh_rows(const float* __restrict__ o, float* __restrict__ out) {
    const int i = blockIdx.x;
    const float* r = o + (size_t)i * NHID;
    float s = 0.f;
    for (int h = threadIdx.x; h < NHID; h += 256) {
        const float a = fabsf(r[h]);
        s += a + log1pf(fast_exp(-2.0f * a));
    }
    #pragma unroll
    for (int off = 16; off > 0; off >>= 1)
        s += __shfl_xor_sync(0xffffffffu, s, off);
    __shared__ float red[8];
    if ((threadIdx.x & 31) == 0) red[threadIdx.x >> 5] = s;
    __syncthreads();
    if (threadIdx.x == 0) {
        float t = 0.f;
        #pragma unroll
        for (int w = 0; w < 8; w++) t += red[w];
        out[i] = t - (float)NHID * 0.6931471805599453f;
    }
}

// ============================================================================
// launch
// ============================================================================
extern "C" void kernel_launch(void* const* d_in, const int* in_sizes, int n_in,
                              void* d_out, int out_size) {
    (void)in_sizes; (void)n_in; (void)out_size;
    const float* x   = (const float*)d_in[0];
    const float* Win = (const float*)d_in[1];
    const float* bin = (const float*)d_in[2];
    const float* Wq  = (const float*)d_in[3];
    const float* Wk  = (const float*)d_in[4];
    const float* Wv  = (const float*)d_in[5];
    float* out = (float*)d_out;

    float* base = nullptr;
    cudaGetSymbolAddress((void**)&base, g_scratch);
    float* S  = base + OFF_S;
    float* h  = base + OFF_H;
    float* q  = base + OFF_Q;
    float* k  = base + OFF_K;
    float* v  = base + OFF_V;
    float* o  = base + OFF_O;
    float* pm = base + OFF_PM;
    float* pz = base + OFF_PZ;
    float* m  = base + OFF_M;
    float* rz = base + OFF_RZ;

    // embedding + q/k/v projections (NT GEMMs, K=1024)
    gemm_kernel<true><<<dim3(NHID / 128, NROW / 128), 256>>>(
        x, Win, h, bin, 1.0f, NROW, NHID, NSPIN);
    gemm_kernel<true><<<dim3(NHID / 128, NROW / 128), 256>>>(
        h, Wq, q, nullptr, 1.0f, NROW, NHID, NHID);
    gemm_kernel<true><<<dim3(NHID / 128, NROW / 128), 256>>>(
        h, Wk, k, nullptr, 1.0f, NROW, NHID, NHID);
    gemm_kernel<true><<<dim3(NHID / 128, NROW / 128), 256>>>(
        h, Wv, v, nullptr, 1.0f, NROW, NHID, NHID);

    // scores S = 0.25 * q @ k^T   [8192, 8192]
    gemm_kernel<true><<<dim3(NROW / 128, NROW / 128), 256>>>(
        q, k, S, nullptr, 0.25f, NROW, NROW, NHID);

    // column softmax stats + in-place P = exp(S - m[j]); fold 1/Z into v
    colmax_part<<<dim3(NROW / 256, CH), 256>>>(S, pm);
    colmax_reduce<<<NROW / 256, 256>>>(pm, m);
    expsum_part<<<dim3(NROW / 256, CH), 256>>>(S, m, pz);
    zreduce<<<NROW / 256, 256>>>(pz, rz);
    scale_v<<<(NROW * NHID) / 256, 256>>>(v, rz);

    // out = P @ v'   (NN GEMM, K=8192)
    gemm_kernel<false><<<dim3(NHID / 128, NROW / 128), 256>>>(
        S, v, o, nullptr, 1.0f, NROW, NHID, NROW);

    // row-wise sum of logcosh
    logcosh_rows<<<NROW, 256>>>(o, out);
}

// round 17
// speedup vs baseline: 1.0003x; 1.0001x over previous
#include <cuda_runtime.h>
#include <cstdint>

// ============================================================================
// SDPA_31671088841439 — GB300 baseline
//   h = x@W_in^T + b; q/k/v = h@W^T; S = 0.25*q@k^T;
//   P = softmax(S, axis=0); out = P@v; result = sum(logcosh(out), -1)
// Strategy: staged fp32 GEMMs using packed fma.rn.f32x2 (2x FFMA throughput
// on sm_103a), column softmax with FMA-pipe polynomial exp (MUFU avoided),
// 1/Z folded into v rows so the second big GEMM stays pure.
// ============================================================================

#define NROW  8192
#define NSPIN 1024
#define NHID  1024
#define CH    16            // row chunks for column reductions
#define RPC   (NROW / CH)   // 512 rows per chunk

// ---------------- scratch (single __device__ global; no allocations) --------
constexpr size_t SZ_S  = (size_t)NROW * NROW;       // 67,108,864
constexpr size_t SZ_NH = (size_t)NROW * NHID;       //  8,388,608
constexpr size_t OFF_S  = 0;
constexpr size_t OFF_H  = OFF_S + SZ_S;
constexpr size_t OFF_Q  = OFF_H + SZ_NH;
constexpr size_t OFF_K  = OFF_Q + SZ_NH;
constexpr size_t OFF_V  = OFF_K + SZ_NH;
constexpr size_t OFF_O  = OFF_V + SZ_NH;
constexpr size_t OFF_PM = OFF_O + SZ_NH;
constexpr size_t OFF_PZ = OFF_PM + (size_t)CH * NROW;
constexpr size_t OFF_M  = OFF_PZ + (size_t)CH * NROW;
constexpr size_t OFF_RZ = OFF_M + NROW;
constexpr size_t SCRATCH_TOTAL = OFF_RZ + NROW;

__device__ float g_scratch[SCRATCH_TOTAL];

// ---------------- packed fp32x2 helpers -------------------------------------
__device__ __forceinline__ unsigned long long pack_dup(float x) {
    unsigned long long r;
    asm("mov.b64 %0, {%1, %1};" : "=l"(r) : "f"(x));
    return r;
}
__device__ __forceinline__ unsigned long long pack2(float x, float y) {
    unsigned long long r;
    asm("mov.b64 %0, {%1, %2};" : "=l"(r) : "f"(x), "f"(y));
    return r;
}
__device__ __forceinline__ void ffma2(unsigned long long& d,
                                      unsigned long long a,
                                      unsigned long long b) {
    asm("fma.rn.f32x2 %0, %1, %2, %0;" : "+l"(d) : "l"(a), "l"(b));
}
__device__ __forceinline__ void unpack2(unsigned long long v, float& lo, float& hi) {
    asm("mov.b64 {%0, %1}, %2;" : "=f"(lo), "=f"(hi) : "l"(v));
}

// ---------------- fast exp on the FMA pipe (args <= 0 in all uses) ----------
// exp(x) = 2^(x*log2e); n = rint(t), r = t-n in [-0.5,0.5]; degree-5 poly for
// 2^r (rel err ~2.4e-6); scale via exponent-bit construction. Clamp t >= -126
// so (n+127) stays a valid normal exponent (underflow -> ~1e-38 ~ 0).
__device__ __forceinline__ float fast_exp(float x) {
    float t = x * 1.4426950408889634f;
    t = fmaxf(t, -126.0f);
    float n = rintf(t);
    float r = t - n;
    float p = 1.3333558e-3f;
    p = fmaf(p, r, 9.6181291e-3f);
    p = fmaf(p, r, 5.5504109e-2f);
    p = fmaf(p, r, 2.4022651e-1f);
    p = fmaf(p, r, 6.9314718e-1f);
    p = fmaf(p, r, 1.0f);
    float s = __int_as_float(((int)n + 127) << 23);
    return p * s;
}

// ============================================================================
// GEMM: C[M,Nn] = alpha * A[M,K] @ op(B) (+ bias[Nn])
//   BT=true : B is [Nn,K] row-major (A@B^T, both K-contiguous)
//   BT=false: B is [K,Nn] row-major (A@B)
// 128x128x8 block tile, 256 threads, 8x8 per thread via fma.rn.f32x2,
// double-buffered smem. All dims are multiples of the tile (8192/1024).
// ============================================================================
template<bool BT>
__global__ __launch_bounds__(256)
void gemm_kernel(const float* __restrict__ A, const float* __restrict__ B,
                 float* __restrict__ C, const float* __restrict__ bias,
                 float alpha, int M, int Nn, int K)
{
    constexpr int BM = 128, BN = 128, BK = 8, PAD = 8;
    __shared__ float As[2][BK][BM + PAD];
    __shared__ float Bs[2][BK][BN + PAD];

    const int tid = threadIdx.x;
    const size_t bm = (size_t)blockIdx.y * BM;
    const size_t bn = (size_t)blockIdx.x * BN;

    // loaders: K-major operands (A always; B when BT): 128 rows x 2 quads
    const int lr = tid >> 1;          // 0..127
    const int lc = (tid & 1) << 2;    // 0 or 4
    // N-major B (NN): 8 rows x 32 quads
    const int nr = tid >> 5;          // 0..7
    const int nc = (tid & 31) << 2;   // 0..124

    // compute mapping: rows ty*8+[0,8), cols {tx*4+[0,4), 64+tx*4+[0,4)}
    const int tx = tid & 15;
    const int ty = tid >> 4;

    const float* Aptr = A + (bm + (size_t)lr) * (size_t)K + lc;
    const float* Bptr = BT ? (B + (bn + (size_t)lr) * (size_t)K + lc)
                           : (B + (size_t)nr * (size_t)Nn + bn + nc);

    unsigned long long acc[8][4];
    #pragma unroll
    for (int i = 0; i < 8; i++)
        #pragma unroll
        for (int j = 0; j < 4; j++) acc[i][j] = 0ULL;

    const int ktiles = K / BK;

    // prologue: tile 0
    float4 aV = *(const float4*)Aptr;
    float4 bV = *(const float4*)Bptr;
    As[0][lc + 0][lr] = aV.x; As[0][lc + 1][lr] = aV.y;
    As[0][lc + 2][lr] = aV.z; As[0][lc + 3][lr] = aV.w;
    if (BT) {
        Bs[0][lc + 0][lr] = bV.x; Bs[0][lc + 1][lr] = bV.y;
        Bs[0][lc + 2][lr] = bV.z; Bs[0][lc + 3][lr] = bV.w;
    } else {
        *(float4*)&Bs[0][nr][nc] = bV;
    }
    __syncthreads();

    int buf = 0;
    for (int kt = 0; kt < ktiles; kt++) {
        if (kt + 1 < ktiles) {
            aV = *(const float4*)(Aptr + (size_t)(kt + 1) * BK);
            if (BT) bV = *(const float4*)(Bptr + (size_t)(kt + 1) * BK);
            else    bV = *(const float4*)(Bptr + (size_t)(kt + 1) * BK * (size_t)Nn);
        }
        #pragma unroll
        for (int k = 0; k < BK; k++) {
            const float4 af0 = *(const float4*)&As[buf][k][ty * 8];
            const float4 af1 = *(const float4*)&As[buf][k][ty * 8 + 4];
            unsigned long long av[8];
            av[0] = pack_dup(af0.x); av[1] = pack_dup(af0.y);
            av[2] = pack_dup(af0.z); av[3] = pack_dup(af0.w);
            av[4] = pack_dup(af1.x); av[5] = pack_dup(af1.y);
            av[6] = pack_dup(af1.z); av[7] = pack_dup(af1.w);
            const float4 bf0 = *(const float4*)&Bs[buf][k][tx * 4];
            const float4 bf1 = *(const float4*)&Bs[buf][k][64 + tx * 4];
            unsigned long long bv[4];
            bv[0] = pack2(bf0.x, bf0.y); bv[1] = pack2(bf0.z, bf0.w);
            bv[2] = pack2(bf1.x, bf1.y); bv[3] = pack2(bf1.z, bf1.w);
            #pragma unroll
            for (int i = 0; i < 8; i++) {
                ffma2(acc[i][0], av[i], bv[0]);
                ffma2(acc[i][1], av[i], bv[1]);
                ffma2(acc[i][2], av[i], bv[2]);
                ffma2(acc[i][3], av[i], bv[3]);
            }
        }
        if (kt + 1 < ktiles) {
            const int nb = buf ^ 1;
            As[nb][lc + 0][lr] = aV.x; As[nb][lc + 1][lr] = aV.y;
            As[nb][lc + 2][lr] = aV.z; As[nb][lc + 3][lr] = aV.w;
            if (BT) {
                Bs[nb][lc + 0][lr] = bV.x; Bs[nb][lc + 1][lr] = bV.y;
                Bs[nb][lc + 2][lr] = bV.z; Bs[nb][lc + 3][lr] = bV.w;
            } else {
                *(float4*)&Bs[nb][nr][nc] = bV;
            }
        }
        __syncthreads();
        buf ^= 1;
    }

    // epilogue
    #pragma unroll
    for (int i = 0; i < 8; i++) {
        float* crow = C + (bm + (size_t)(ty * 8 + i)) * (size_t)Nn + bn;
        #pragma unroll
        for (int h = 0; h < 2; h++) {
            const int col = h * 64 + tx * 4;
            float x0, x1, x2, x3;
            unpack2(acc[i][h * 2 + 0], x0, x1);
            unpack2(acc[i][h * 2 + 1], x2, x3);
            float4 o;
            o.x = alpha * x0; o.y = alpha * x1;
            o.z = alpha * x2; o.w = alpha * x3;
            if (bias != nullptr) {
                const float4 bb = *(const float4*)&bias[bn + col];
                o.x += bb.x; o.y += bb.y; o.z += bb.z; o.w += bb.w;
            }
            *(float4*)&crow[col] = o;
        }
    }
}

// ============================================================================
// Column softmax (axis=0): per column j over rows i of S[8192,8192]
// ============================================================================
__global__ void colmax_part(const float* __restrict__ S, float* __restrict__ pm) {
    const int j = blockIdx.x * blockDim.x + threadIdx.x;
    const int c = blockIdx.y;
    const float* p = S + (size_t)c * RPC * NROW + j;
    float m0 = -3.4e38f, m1 = m0, m2 = m0, m3 = m0;
    float m4 = m0, m5 = m0, m6 = m0, m7 = m0;
    for (int i = 0; i < RPC; i += 8) {
        m0 = fmaxf(m0, p[(size_t)(i + 0) * NROW]);
        m1 = fmaxf(m1, p[(size_t)(i + 1) * NROW]);
        m2 = fmaxf(m2, p[(size_t)(i + 2) * NROW]);
        m3 = fmaxf(m3, p[(size_t)(i + 3) * NROW]);
        m4 = fmaxf(m4, p[(size_t)(i + 4) * NROW]);
        m5 = fmaxf(m5, p[(size_t)(i + 5) * NROW]);
        m6 = fmaxf(m6, p[(size_t)(i + 6) * NROW]);
        m7 = fmaxf(m7, p[(size_t)(i + 7) * NROW]);
    }
    pm[(size_t)c * NROW + j] =
        fmaxf(fmaxf(fmaxf(m0, m1), fmaxf(m2, m3)),
              fmaxf(fmaxf(m4, m5), fmaxf(m6, m7)));
}

__global__ void colmax_reduce(const float* __restrict__ pm, float* __restrict__ m) {
    const int j = blockIdx.x * blockDim.x + threadIdx.x;
    float mx = pm[j];
    #pragma unroll
    for (int c = 1; c < CH; c++) mx = fmaxf(mx, pm[(size_t)c * NROW + j]);
    m[j] = mx;
}

// P = exp(S - m[j]) written in place; per-chunk partial column sums
__global__ void expsum_part(float* __restrict__ S, const float* __restrict__ m,
                            float* __restrict__ pz) {
    const int j = blockIdx.x * blockDim.x + threadIdx.x;
    const int c = blockIdx.y;
    const float mj = m[j];
    float* p = S + (size_t)c * RPC * NROW + j;
    float z0 = 0.f, z1 = 0.f, z2 = 0.f, z3 = 0.f;
    for (int i = 0; i < RPC; i += 4) {
        float e0 = fast_exp(p[(size_t)(i + 0) * NROW] - mj);
        float e1 = fast_exp(p[(size_t)(i + 1) * NROW] - mj);
        float e2 = fast_exp(p[(size_t)(i + 2) * NROW] - mj);
        float e3 = fast_exp(p[(size_t)(i + 3) * NROW] - mj);
        p[(size_t)(i + 0) * NROW] = e0;
        p[(size_t)(i + 1) * NROW] = e1;
        p[(size_t)(i + 2) * NROW] = e2;
        p[(size_t)(i + 3) * NROW] = e3;
        z0 += e0; z1 += e1; z2 += e2; z3 += e3;
    }
    pz[(size_t)c * NROW + j] = (z0 + z1) + (z2 + z3);
}

__global__ void zreduce(const float* __restrict__ pz, float* __restrict__ rz) {
    const int j = blockIdx.x * blockDim.x + threadIdx.x;
    float z = 0.f;
    #pragma unroll
    for (int c = 0; c < CH; c++) z += pz[(size_t)c * NROW + j];
    rz[j] = 1.0f / z;
}

// v'[j,h] = v[j,h] / Z[j]  (fold softmax denominator into v rows)
__global__ void scale_v(float* __restrict__ v, const float* __restrict__ rz) {
    const size_t idx = (size_t)blockIdx.x * blockDim.x + threadIdx.x;
    v[idx] *= rz[idx >> 10];  // NHID = 1024
}

// ============================================================================
// result[i] = sum_h logcosh(o[i,h]) ; logcosh(z)=|z|+log1p(exp(-2|z|))-ln2
// ============================================================================
__global__ void logcosh_rows(const float* __restrict__ o, float* __restrict__ out) {
    const int i = blockIdx.x;
    const float* r = o + (size_t)i * NHID;
    float s = 0.f;
    for (int h = threadIdx.x; h < NHID; h += 256) {
        const float a = fabsf(r[h]);
        s += a + log1pf(fast_exp(-2.0f * a));
    }
    #pragma unroll
    for (int off = 16; off > 0; off >>= 1)
        s += __shfl_xor_sync(0xffffffffu, s, off);
    __shared__ float red[8];
    if ((threadIdx.x & 31) == 0) red[threadIdx.x >> 5] = s;
    __syncthreads();
    if (threadIdx.x == 0) {
        float t = 0.f;
        #pragma unroll
        for (int w = 0; w < 8; w++) t += red[w];
        out[i] = t - (float)NHID * 0.6931471805599453f;
    }
}

// ============================================================================
// launch
// ============================================================================
extern "C" void kernel_launch(void* const* d_in, const int* in_sizes, int n_in,
                              void* d_out, int out_size) {
    (void)in_sizes; (void)n_in; (void)out_size;
    const float* x   = (const float*)d_in[0];
    const float* Win = (const float*)d_in[1];
    const float* bin = (const float*)d_in[2];
    const float* Wq  = (const float*)d_in[3];
    const float* Wk  = (const float*)d_in[4];
    const float* Wv  = (const float*)d_in[5];
    float* out = (float*)d_out;

    float* base = nullptr;
    cudaGetSymbolAddress((void**)&base, g_scratch);
    float* S  = base + OFF_S;
    float* h  = base + OFF_H;
    float* q  = base + OFF_Q;
    float* k  = base + OFF_K;
    float* v  = base + OFF_V;
    float* o  = base + OFF_O;
    float* pm = base + OFF_PM;
    float* pz = base + OFF_PZ;
    float* m  = base + OFF_M;
    float* rz = base + OFF_RZ;

    // embedding + q/k/v projections (NT GEMMs, K=1024)
    gemm_kernel<true><<<dim3(NHID / 128, NROW / 128), 256>>>(
        x, Win, h, bin, 1.0f, NROW, NHID, NSPIN);
    gemm_kernel<true><<<dim3(NHID / 128, NROW / 128), 256>>>(
        h, Wq, q, nullptr, 1.0f, NROW, NHID, NHID);
    gemm_kernel<true><<<dim3(NHID / 128, NROW / 128), 256>>>(
        h, Wk, k, nullptr, 1.0f, NROW, NHID, NHID);
    gemm_kernel<true><<<dim3(NHID / 128, NROW / 128), 256>>>(
        h, Wv, v, nullptr, 1.0f, NROW, NHID, NHID);

    // scores S = 0.25 * q @ k^T   [8192, 8192]
    gemm_kernel<true><<<dim3(NROW / 128, NROW / 128), 256>>>(
        q, k, S, nullptr, 0.25f, NROW, NROW, NHID);

    // column softmax stats + in-place P = exp(S - m[j]); fold 1/Z into v
    colmax_part<<<dim3(NROW / 256, CH), 256>>>(S, pm);
    colmax_reduce<<<NROW / 256, 256>>>(pm, m);
    expsum_part<<<dim3(NROW / 256, CH), 256>>>(S, m, pz);
    zreduce<<<NROW / 256, 256>>>(pz, rz);
    scale_v<<<(NROW * NHID) / 256, 256>>>(v, rz);

    // out = P @ v'   (NN GEMM, K=8192)
    gemm_kernel<false><<<dim3(NHID / 128, NROW / 128), 256>>>(
        S, v, o, nullptr, 1.0f, NROW, NHID, NROW);

    // row-wise sum of logcosh
    logcosh_rows<<<NROW, 256>>>(o, out);
}